// round 2
// baseline (speedup 1.0000x reference)
#include <cuda_runtime.h>
#include <math_constants.h>

// Problem constants
#define DD 256
#define TT 4096
#define BBATCH 16
#define KK 1024
#define NTOK (BBATCH * TT)                  // 65536 tokens
#define NDATA ((size_t)BBATCH * DD * TT)    // 16777216 output data elements

// Scratch (no cudaMalloc allowed)
__device__ float  g_e2[KK];
__device__ int    g_idx[NTOK];
__device__ double g_loss_sum;

// Packed fp32x2 FMA: both lanes are exact fp32 fma.rn -> bit-identical to the
// scalar fmaf chain per accumulator.
#define FMA2(c, a, b) \
    asm("fma.rn.f32x2 %0, %1, %2, %0;" : "+l"(c) : "l"(a), "l"(b))

// ---------------------------------------------------------------------------
// Kernel 0: per-code ||e_k||^2 (sequential mul-then-add, like jnp.sum(emb*emb))
//           + zero the loss accumulator for this replay.
// ---------------------------------------------------------------------------
__global__ void vq_prep_kernel(const float* __restrict__ emb) {
    int k = blockIdx.x * blockDim.x + threadIdx.x;
    if (k == 0) g_loss_sum = 0.0;
    if (k < KK) {
        const float* e = emb + (size_t)k * DD;
        float acc = 0.0f;
        #pragma unroll 8
        for (int d = 0; d < DD; ++d) {
            float v = e[d];
            acc = __fadd_rn(acc, __fmul_rn(v, v));
        }
        g_e2[k] = acc;
    }
}

// ---------------------------------------------------------------------------
// Kernel 1: fused GEMM + argmin, f32x2-packed.
// Block: 256 threads = 8(tx: token octets) x 32(ty: code octets).
// Tile: 64 tokens x 256 codes per n-chunk, 8x8 per thread (32 packed b64 accs),
// K=256 in 32-d chunks.
// zs [256 d][64 tok] resident (64KB); a-side loads are 2x LDS.128 giving
// naturally packed token pairs (zero pack MOVs). es chunk [32 d][257-stride
// codes]: conflict-free stores (stride 257) and 4-address-broadcast loads.
// Accumulation: strictly sequential ascending-d fused fma.rn per output
// (bit-matches Eigen/cuBLAS fp32 micro-kernel accumulation).
// dist = fl(fl(r2 + e2) - fl(2*mm)) exactly as the reference expression.
// ---------------------------------------------------------------------------
#define ZS_FLOATS (DD * 64)          // 16384
#define ES_STRIDE 257
#define ES_FLOATS (32 * ES_STRIDE)   // 8224
#define SMEM_FLOATS (ZS_FLOATS + ES_FLOATS + 64)
#define SMEM_BYTES (SMEM_FLOATS * 4)

extern "C" __global__ void __launch_bounds__(256, 2)
vq_argmin_kernel(const float* __restrict__ z, const float* __restrict__ emb) {
    extern __shared__ float smem[];
    float* zs  = smem;                        // [d][tok], d-major
    float* es  = smem + ZS_FLOATS;            // [dl][code], stride 257
    float* r2s = smem + ZS_FLOATS + ES_FLOATS;

    const int tid = threadIdx.x;
    const int tx  = tid & 7;                  // token octet
    const int ty  = tid >> 3;                 // code octet (0..31)
    const int tile0 = blockIdx.x << 6;        // first token of tile
    const int b  = tile0 >> 12;               // 4096 tokens per batch; tiles never cross b
    const int t0 = tile0 & 4095;
    const float* zb = z + (size_t)b * DD * TT + t0;

    // Load z tile: coalesced (64 contiguous t per d), conflict-free store.
    for (int e = tid; e < DD * 64; e += 256) {
        int d = e >> 6, i = e & 63;
        zs[(d << 6) + i] = zb[(size_t)d * TT + i];
    }
    __syncthreads();

    // r2 per token: sequential mul-then-add (order-insensitive by
    // uniform-ulp-shift: shifting every dist by the same grid multiple leaves
    // argmin and ties invariant).
    if (tid < 64) {
        float acc = 0.0f;
        #pragma unroll 8
        for (int d = 0; d < DD; ++d) {
            float v = zs[(d << 6) + tid];
            acc = __fadd_rn(acc, __fmul_rn(v, v));
        }
        r2s[tid] = acc;
    }
    __syncthreads();

    float r2v[8];
    #pragma unroll
    for (int ii = 0; ii < 8; ++ii) r2v[ii] = r2s[(tx << 3) + ii];

    float bval[8];
    int   bidx[8];
    #pragma unroll
    for (int ii = 0; ii < 8; ++ii) { bval[ii] = CUDART_INF_F; bidx[ii] = 0; }

    for (int nc = 0; nc < KK; nc += 256) {
        // acc[p][j]: token pair p (tokens 2p,2p+1 in lo,hi) x code j
        unsigned long long acc[4][8];
        #pragma unroll
        for (int p = 0; p < 4; ++p)
            #pragma unroll
            for (int j = 0; j < 8; ++j) acc[p][j] = 0ull;

        for (int kc = 0; kc < DD; kc += 32) {
            __syncthreads();  // protect es from previous chunk's readers
            // Fill es: gmem coalesced (dl contiguous per warp), smem stride-257
            // stores conflict-free.
            for (int e = tid; e < 32 * 256; e += 256) {
                int dl = e & 31, code = e >> 5;
                es[dl * ES_STRIDE + code] =
                    emb[((size_t)(nc + code) << 8) + kc + dl];
            }
            __syncthreads();

            #pragma unroll 8
            for (int dl = 0; dl < 32; ++dl) {
                const float* zrow = &zs[((kc + dl) << 6) + (tx << 3)];
                ulonglong2 A0 = *(const ulonglong2*)zrow;        // tokens 0-3
                ulonglong2 A1 = *(const ulonglong2*)(zrow + 4);  // tokens 4-7
                const float* brow = &es[dl * ES_STRIDE + (ty << 3)];
                #pragma unroll
                for (int j = 0; j < 8; ++j) {
                    unsigned bu = __float_as_uint(brow[j]);
                    unsigned long long bb;
                    asm("mov.b64 %0, {%1, %1};" : "=l"(bb) : "r"(bu));
                    FMA2(acc[0][j], A0.x, bb);
                    FMA2(acc[1][j], A0.y, bb);
                    FMA2(acc[2][j], A1.x, bb);
                    FMA2(acc[3][j], A1.y, bb);
                }
            }
        }

        // Scores: replicate fl(fl(r2+e2) - fl(2*mm)); ascending code order,
        // strict < keeps the first (lowest-index) minimum.
        #pragma unroll
        for (int j = 0; j < 8; ++j) {
            int code = nc + (ty << 3) + j;
            float e2v = g_e2[code];
            #pragma unroll
            for (int p = 0; p < 4; ++p) {
                unsigned lo, hi;
                asm("mov.b64 {%0, %1}, %2;"
                    : "=r"(lo), "=r"(hi) : "l"(acc[p][j]));
                float d0 = __fsub_rn(__fadd_rn(r2v[2 * p], e2v),
                                     __fmul_rn(2.0f, __uint_as_float(lo)));
                if (d0 < bval[2 * p]) { bval[2 * p] = d0; bidx[2 * p] = code; }
                float d1 = __fsub_rn(__fadd_rn(r2v[2 * p + 1], e2v),
                                     __fmul_rn(2.0f, __uint_as_float(hi)));
                if (d1 < bval[2 * p + 1]) {
                    bval[2 * p + 1] = d1; bidx[2 * p + 1] = code;
                }
            }
        }
    }

    // Cross-ty reduction (32 partials per token), tie -> lowest index.
    __syncthreads();
    float* redv = es;                 // 32*64 floats
    int*   redi = (int*)(es + 2048);  // 32*64 ints
    #pragma unroll
    for (int ii = 0; ii < 8; ++ii) {
        redv[(ty << 6) + (tx << 3) + ii] = bval[ii];
        redi[(ty << 6) + (tx << 3) + ii] = bidx[ii];
    }
    __syncthreads();
    if (tid < 64) {
        float bv = redv[tid];
        int   bi = redi[tid];
        #pragma unroll
        for (int y = 1; y < 32; ++y) {
            float v  = redv[(y << 6) + tid];
            int   i2 = redi[(y << 6) + tid];
            if (v < bv || (v == bv && i2 < bi)) { bv = v; bi = i2; }
        }
        g_idx[tile0 + tid] = bi;
    }
}

// ---------------------------------------------------------------------------
// Kernel 2: gather + straight-through output + loss partial sums.
// out[b,d,t] = fl(z + fl(q - z)) — replicates the reference STE arithmetic.
// Loss terms fl((q-z)^2) accumulated in double.
// ---------------------------------------------------------------------------
__global__ void vq_output_kernel(const float* __restrict__ z,
                                 const float* __restrict__ emb,
                                 float* __restrict__ out) {
    double local = 0.0;
    size_t stride = (size_t)gridDim.x * blockDim.x;
    for (size_t e = (size_t)blockIdx.x * blockDim.x + threadIdx.x; e < NDATA; e += stride) {
        int t  = (int)(e & 4095);
        int d  = (int)((e >> 12) & 255);
        int bb = (int)(e >> 20);
        int idx = g_idx[(bb << 12) + t];
        float q  = __ldg(&emb[((size_t)idx << 8) + d]);
        float zv = z[e];
        float diff = __fsub_rn(q, zv);
        out[e] = __fadd_rn(zv, diff);
        float dsq = __fmul_rn(diff, diff);
        local += (double)dsq;
    }
    // Warp + block reduction, one atomic per block.
    #pragma unroll
    for (int off = 16; off > 0; off >>= 1)
        local += __shfl_down_sync(0xffffffffu, local, off);
    __shared__ double wsum[8];
    int lane = threadIdx.x & 31, wid = threadIdx.x >> 5;
    if (lane == 0) wsum[wid] = local;
    __syncthreads();
    if (threadIdx.x == 0) {
        double s = 0.0;
        #pragma unroll
        for (int i = 0; i < 8; ++i) s += wsum[i];
        atomicAdd(&g_loss_sum, s);
    }
}

// ---------------------------------------------------------------------------
// Kernel 3: finalize loss = fl(m + fl(0.25*m)), m = mean in fp32.
// ---------------------------------------------------------------------------
__global__ void vq_finalize_kernel(float* __restrict__ out, int out_size) {
    if (threadIdx.x == 0 && blockIdx.x == 0) {
        if ((size_t)out_size > NDATA) {
            float m = (float)(g_loss_sum * (1.0 / 16777216.0));  // exact /2^24
            out[NDATA] = __fadd_rn(m, __fmul_rn(0.25f, m));
        }
    }
}

// ---------------------------------------------------------------------------
extern "C" void kernel_launch(void* const* d_in, const int* in_sizes, int n_in,
                              void* d_out, int out_size) {
    const float* z   = (const float*)d_in[0];
    const float* emb = (const float*)d_in[1];
    // Defensive: detect swapped input order by element counts.
    if (n_in >= 2 && in_sizes[0] == KK * DD && (size_t)in_sizes[1] == NDATA) {
        const float* tmp = z; z = emb; emb = tmp;
    }
    float* out = (float*)d_out;

    cudaFuncSetAttribute((const void*)vq_argmin_kernel,
                         cudaFuncAttributeMaxDynamicSharedMemorySize, SMEM_BYTES);

    vq_prep_kernel<<<4, 256>>>(emb);
    vq_argmin_kernel<<<NTOK / 64, 256, SMEM_BYTES>>>(z, emb);
    vq_output_kernel<<<2048, 256>>>(z, emb, out);
    vq_finalize_kernel<<<1, 32>>>(out, out_size);
}